// round 2
// baseline (speedup 1.0000x reference)
#include <cuda_runtime.h>

// Problem constants
#define BATCH   8
#define CH      512
#define HEADS   8
#define HD      64          // CH / HEADS
#define GROUPS  32
#define CPG     (CH / GROUPS)   // 16
#define NPIX    1024        // 32*32
#define EPS_GN  1e-6f
#define CHB     8           // (b,h) pairs per attention chunk (S buffer size)

// -------- scratch (device globals — allocation-free rule) ----------
// Keep total small: previous 336 MB OOM'd the container.
__device__ float g_qkv[BATCH * 3 * CH * NPIX];        // 48 MB  qkv projections
__device__ float g_S  [CHB * NPIX * NPIX];            // 32 MB  S chunk (reused 8x)
__device__ float g_ao [BATCH * CH * NPIX];            // 16 MB  attention output
__device__ float g_sc [BATCH * CH];                   // per (b,c) scale for fused GN
__device__ float g_tb [BATCH * CH];                   // per (b,c) shift for fused GN

// =====================================================================
// 1) GroupNorm stats: one block per (b, group). Produces per-channel
//    affine (s, t) so that xn = x*s + t, consumed by the QKV GEMM.
// =====================================================================
__global__ void __launch_bounds__(256) gn_stats_kernel(
    const float* __restrict__ x,
    const float* __restrict__ gamma,
    const float* __restrict__ beta)
{
    const int bg = blockIdx.x;
    const int b  = bg / GROUPS;
    const int g  = bg % GROUPS;
    const int elems = CPG * NPIX;   // 16384
    const float* xp = x + ((size_t)b * CH + g * CPG) * NPIX;

    float s = 0.f, sq = 0.f;
    for (int i = threadIdx.x; i < elems; i += 256) {
        float v = xp[i];
        s += v; sq += v * v;
    }
    __shared__ float rs[256], rq[256];
    rs[threadIdx.x] = s; rq[threadIdx.x] = sq;
    __syncthreads();
    for (int st = 128; st > 0; st >>= 1) {
        if (threadIdx.x < st) {
            rs[threadIdx.x] += rs[threadIdx.x + st];
            rq[threadIdx.x] += rq[threadIdx.x + st];
        }
        __syncthreads();
    }
    const float mean = rs[0] * (1.f / elems);
    const float var  = rq[0] * (1.f / elems) - mean * mean;
    const float inv  = rsqrtf(var + EPS_GN);

    if (threadIdx.x < CPG) {
        const int ch = g * CPG + threadIdx.x;
        const float sc = inv * gamma[ch];
        g_sc[b * CH + ch] = sc;
        g_tb[b * CH + ch] = beta[ch] - mean * sc;
    }
}

// =====================================================================
// 2) Weight GEMM: C[b][o][n] = sum_c W[o][c]*(X[b][c][n]*s+t) + bias[o] (+res)
//    128x128 tile, BK=8, 256 threads, 8x8 microtile.
// =====================================================================
__global__ void __launch_bounds__(256) wgemm_kernel(
    const float* __restrict__ W,     // [M][K] row-major
    const float* __restrict__ bias,  // [M]
    const float* __restrict__ X,     // [batch][K][NPIX]
    const float* __restrict__ sc,    // [batch][K] or null (fused GN scale)
    const float* __restrict__ tb,    // [batch][K] or null (fused GN shift)
    const float* __restrict__ res,   // [batch][M][NPIX] or null
    float* __restrict__ C,           // [batch][M][NPIX]
    int Kdim)
{
    __shared__ float As[8][128];
    __shared__ float Bs[8][128];

    const int bz = blockIdx.z;
    const float* Xb = X + (size_t)bz * Kdim * NPIX;
    float*       Cb = C;  // offset below
    const float* scb = sc ? sc + bz * Kdim : nullptr;
    const float* tbb = tb ? tb + bz * Kdim : nullptr;

    const int o0 = blockIdx.y * 128;
    const int n0 = blockIdx.x * 128;
    const int tid = threadIdx.x;

    const int a_row = tid >> 1;          // 0..127
    const int a_col = (tid & 1) * 4;     // 0 or 4
    const int b_row = tid >> 5;          // 0..7
    const int b_col = (tid & 31) * 4;    // 0..124
    const int ty = tid >> 4, tx = tid & 15;

    float acc[8][8] = {};

    for (int k0 = 0; k0 < Kdim; k0 += 8) {
        float4 av = *(const float4*)&W[(size_t)(o0 + a_row) * Kdim + k0 + a_col];
        As[a_col + 0][a_row] = av.x;
        As[a_col + 1][a_row] = av.y;
        As[a_col + 2][a_row] = av.z;
        As[a_col + 3][a_row] = av.w;
        float4 bv = *(const float4*)&Xb[(size_t)(k0 + b_row) * NPIX + n0 + b_col];
        if (scb) {
            const float s = scb[k0 + b_row];
            const float t = tbb[k0 + b_row];
            bv.x = bv.x * s + t; bv.y = bv.y * s + t;
            bv.z = bv.z * s + t; bv.w = bv.w * s + t;
        }
        *(float4*)&Bs[b_row][b_col] = bv;
        __syncthreads();

        #pragma unroll
        for (int kk = 0; kk < 8; kk++) {
            float a[8], bb[8];
            #pragma unroll
            for (int i = 0; i < 8; i++) a[i]  = As[kk][ty * 8 + i];
            #pragma unroll
            for (int j = 0; j < 8; j++) bb[j] = Bs[kk][tx * 8 + j];
            #pragma unroll
            for (int i = 0; i < 8; i++)
                #pragma unroll
                for (int j = 0; j < 8; j++)
                    acc[i][j] += a[i] * bb[j];
        }
        __syncthreads();
    }

    const int Mstride = gridDim.y * 128;
    Cb = C + (size_t)bz * Mstride * NPIX;
    const float* Rb = res ? res + (size_t)bz * Mstride * NPIX : nullptr;

    #pragma unroll
    for (int i = 0; i < 8; i++) {
        const int o = o0 + ty * 8 + i;
        const float bvs = bias[o];
        #pragma unroll
        for (int j = 0; j < 8; j++) {
            const int n = n0 + tx * 8 + j;
            float v = acc[i][j] + bvs;
            if (Rb) v += Rb[(size_t)o * NPIX + n];
            Cb[(size_t)o * NPIX + n] = v;
        }
    }
}

// =====================================================================
// 3) QK^T chunk: S[bhl][n][m] = scale * sum_d q[d][n]*k[d][m]
// =====================================================================
__global__ void __launch_bounds__(256) qk_kernel(int bh0)
{
    __shared__ float Qs[8][128];
    __shared__ float Ks[8][128];

    const int bhl = blockIdx.z;          // local chunk index
    const int bh = bh0 + bhl;
    const int b = bh >> 3, h = bh & 7;
    const float* q = g_qkv + ((size_t)b * 3 * CH + h * HD) * NPIX;
    const float* k = g_qkv + ((size_t)b * 3 * CH + CH + h * HD) * NPIX;
    float* Sb = g_S + (size_t)bhl * NPIX * NPIX;

    const int n0 = blockIdx.y * 128;
    const int m0 = blockIdx.x * 128;
    const int tid = threadIdx.x;
    const int l_row = tid >> 5, l_col = (tid & 31) * 4;
    const int ty = tid >> 4, tx = tid & 15;

    float acc[8][8] = {};

    for (int d0 = 0; d0 < HD; d0 += 8) {
        *(float4*)&Qs[l_row][l_col] =
            *(const float4*)&q[(size_t)(d0 + l_row) * NPIX + n0 + l_col];
        *(float4*)&Ks[l_row][l_col] =
            *(const float4*)&k[(size_t)(d0 + l_row) * NPIX + m0 + l_col];
        __syncthreads();

        #pragma unroll
        for (int kk = 0; kk < 8; kk++) {
            float a[8], bb[8];
            #pragma unroll
            for (int i = 0; i < 8; i++) a[i]  = Qs[kk][ty * 8 + i];
            #pragma unroll
            for (int j = 0; j < 8; j++) bb[j] = Ks[kk][tx * 8 + j];
            #pragma unroll
            for (int i = 0; i < 8; i++)
                #pragma unroll
                for (int j = 0; j < 8; j++)
                    acc[i][j] += a[i] * bb[j];
        }
        __syncthreads();
    }

    const float scale = 0.125f;   // hd^-0.5 = 1/8
    #pragma unroll
    for (int i = 0; i < 8; i++)
        #pragma unroll
        for (int j = 0; j < 8; j++)
            Sb[(size_t)(n0 + ty * 8 + i) * NPIX + m0 + tx * 8 + j] = acc[i][j] * scale;
}

// =====================================================================
// 4) Row softmax over m (length 1024). grid(1024, CHB), 128 threads.
// =====================================================================
__global__ void __launch_bounds__(128) softmax_kernel()
{
    float* r = g_S + ((size_t)blockIdx.y * NPIX + blockIdx.x) * NPIX;
    const int t = threadIdx.x;
    __shared__ float red[128];

    float v[8];
    float m = -1e30f;
    #pragma unroll
    for (int i = 0; i < 8; i++) {
        v[i] = r[t + i * 128];
        m = fmaxf(m, v[i]);
    }
    red[t] = m; __syncthreads();
    for (int st = 64; st > 0; st >>= 1) {
        if (t < st) red[t] = fmaxf(red[t], red[t + st]);
        __syncthreads();
    }
    m = red[0];
    __syncthreads();

    float s = 0.f;
    #pragma unroll
    for (int i = 0; i < 8; i++) {
        v[i] = __expf(v[i] - m);
        s += v[i];
    }
    red[t] = s; __syncthreads();
    for (int st = 64; st > 0; st >>= 1) {
        if (t < st) red[t] += red[t + st];
        __syncthreads();
    }
    const float inv = 1.f / red[0];
    #pragma unroll
    for (int i = 0; i < 8; i++) r[t + i * 128] = v[i] * inv;
}

// =====================================================================
// 5) AV chunk: ao[bh][d][n] = sum_m P[n][m] * v[d][m]
//    Tile 64(d) x 128(n), BK=16 over m, 256 threads, 4x8 microtile.
//    n-mapping stride-16 for conflict-free Ps reads.
// =====================================================================
__global__ void __launch_bounds__(256) av_kernel(int bh0)
{
    __shared__ float Vs[16][64];    // Vs[k][d]
    __shared__ float Ps[16][128];   // Ps[k][n]

    const int bhl = blockIdx.y;
    const int bh = bh0 + bhl;
    const int b = bh >> 3, h = bh & 7;
    const float* V  = g_qkv + ((size_t)b * 3 * CH + 2 * CH + h * HD) * NPIX;
    const float* Sb = g_S + (size_t)bhl * NPIX * NPIX;
    float* ao = g_ao + ((size_t)b * CH + h * HD) * NPIX;

    const int n0 = blockIdx.x * 128;
    const int tid = threadIdx.x;
    const int trow = tid >> 4;          // 0..15 -> d rows * 4
    const int tcol = tid & 15;          // n cols, stride-16
    const int vr = tid >> 2;            // 0..63
    const int vk = (tid & 3) * 4;       // 0..12

    float acc[4][8] = {};

    for (int m0 = 0; m0 < NPIX; m0 += 16) {
        float4 vv = *(const float4*)&V[(size_t)vr * NPIX + m0 + vk];
        Vs[vk + 0][vr] = vv.x;
        Vs[vk + 1][vr] = vv.y;
        Vs[vk + 2][vr] = vv.z;
        Vs[vk + 3][vr] = vv.w;
        #pragma unroll
        for (int l = 0; l < 2; l++) {
            int idx = tid * 2 + l;      // 0..511
            int pr  = idx >> 2;         // n row 0..127
            int pk  = (idx & 3) * 4;
            float4 pv = *(const float4*)&Sb[(size_t)(n0 + pr) * NPIX + m0 + pk];
            Ps[pk + 0][pr] = pv.x;
            Ps[pk + 1][pr] = pv.y;
            Ps[pk + 2][pr] = pv.z;
            Ps[pk + 3][pr] = pv.w;
        }
        __syncthreads();

        #pragma unroll
        for (int kk = 0; kk < 16; kk++) {
            float a[4], bb[8];
            #pragma unroll
            for (int i = 0; i < 4; i++) a[i]  = Vs[kk][trow * 4 + i];
            #pragma unroll
            for (int j = 0; j < 8; j++) bb[j] = Ps[kk][tcol + 16 * j];
            #pragma unroll
            for (int i = 0; i < 4; i++)
                #pragma unroll
                for (int j = 0; j < 8; j++)
                    acc[i][j] += a[i] * bb[j];
        }
        __syncthreads();
    }

    #pragma unroll
    for (int i = 0; i < 4; i++)
        #pragma unroll
        for (int j = 0; j < 8; j++)
            ao[(size_t)(trow * 4 + i) * NPIX + n0 + tcol + 16 * j] = acc[i][j];
}

// =====================================================================
// launcher
// =====================================================================
extern "C" void kernel_launch(void* const* d_in, const int* in_sizes, int n_in,
                              void* d_out, int out_size)
{
    const float* x      = (const float*)d_in[0];
    const float* norm_w = (const float*)d_in[1];
    const float* norm_b = (const float*)d_in[2];
    const float* qkv_w  = (const float*)d_in[3];
    const float* qkv_b  = (const float*)d_in[4];
    const float* proj_w = (const float*)d_in[5];
    const float* proj_b = (const float*)d_in[6];
    float* out = (float*)d_out;

    float *qkv_p, *sc_p, *tb_p, *ao_p;
    cudaGetSymbolAddress((void**)&qkv_p, g_qkv);
    cudaGetSymbolAddress((void**)&sc_p,  g_sc);
    cudaGetSymbolAddress((void**)&tb_p,  g_tb);
    cudaGetSymbolAddress((void**)&ao_p,  g_ao);

    // 1) GroupNorm stats -> per-channel affine
    gn_stats_kernel<<<BATCH * GROUPS, 256>>>(x, norm_w, norm_b);

    // 2) QKV projection with fused GN: M=1536, K=512
    {
        dim3 grid(NPIX / 128, (3 * CH) / 128, BATCH);
        wgemm_kernel<<<grid, 256>>>(qkv_w, qkv_b, x, sc_p, tb_p,
                                    nullptr, qkv_p, CH);
    }

    // 3-5) attention in chunks of CHB (b,h) pairs, reusing the S buffer.
    for (int bh0 = 0; bh0 < BATCH * HEADS; bh0 += CHB) {
        {
            dim3 grid(NPIX / 128, NPIX / 128, CHB);
            qk_kernel<<<grid, 256>>>(bh0);
        }
        {
            dim3 grid(NPIX, CHB);
            softmax_kernel<<<grid, 128>>>();
        }
        {
            dim3 grid(NPIX / 128, CHB);
            av_kernel<<<grid, 256>>>(bh0);
        }
    }

    // 6) proj + bias + residual: M=512, K=512
    {
        dim3 grid(NPIX / 128, CH / 128, BATCH);
        wgemm_kernel<<<grid, 256>>>(proj_w, proj_b, ao_p, nullptr, nullptr,
                                    x, out, CH);
    }
}